// round 14
// baseline (speedup 1.0000x reference)
#include <cuda_runtime.h>
#include <cuda_fp16.h>
#include <cstdint>

#define BBt 4
#define SS 512
#define INs 512
#define OUTs 112
#define N1 57344

static __device__ __half g_th[117440512 + 256];  // t[bx][o*512+j], fp16
static __device__ __half g_wh[29360128];         // w1 fp16, native [k][n] layout
static __device__ __half g_in1h[2097152];
static __device__ __half g_in2h[2097152];
static __device__ float  g_termA[229376];        // termA[bx][o] + bias
static __device__ float  g_termB[229376];        // termB[b*S+y][o]

// ---------------- helpers ----------------------------------------------------
__device__ __forceinline__ uint32_t smem_u32(const void* p) {
    uint32_t a;
    asm("{ .reg .u64 t; cvta.to.shared.u64 t, %1; cvt.u32.u64 %0, t; }" : "=r"(a) : "l"(p));
    return a;
}
__device__ __forceinline__ void cp16(uint32_t dst, const void* src) {
    asm volatile("cp.async.cg.shared.global [%0], [%1], 16;\n" :: "r"(dst), "l"(src));
}
#define CP_COMMIT() asm volatile("cp.async.commit_group;\n" ::: "memory")
#define CP_WAIT0()  asm volatile("cp.async.wait_group 0;\n" ::: "memory")
#define CP_WAIT1()  asm volatile("cp.async.wait_group 1;\n" ::: "memory")

__device__ __forceinline__ void ldsm4(uint32_t* r, uint32_t addr) {
    asm volatile("ldmatrix.sync.aligned.m8n8.x4.shared.b16 {%0,%1,%2,%3}, [%4];"
        : "=r"(r[0]), "=r"(r[1]), "=r"(r[2]), "=r"(r[3]) : "r"(addr));
}
__device__ __forceinline__ void ldsm4t(uint32_t* r, uint32_t addr) {
    asm volatile("ldmatrix.sync.aligned.m8n8.x4.trans.shared.b16 {%0,%1,%2,%3}, [%4];"
        : "=r"(r[0]), "=r"(r[1]), "=r"(r[2]), "=r"(r[3]) : "r"(addr));
}
__device__ __forceinline__ void ldsm2(uint32_t* r, uint32_t addr) {
    asm volatile("ldmatrix.sync.aligned.m8n8.x2.shared.b16 {%0,%1}, [%2];"
        : "=r"(r[0]), "=r"(r[1]) : "r"(addr));
}
// m16n8k16 fp16 mma, row.col, f32 accum
__device__ __forceinline__ void mma16(float* d, const uint32_t* a, const uint32_t* b) {
    asm volatile("mma.sync.aligned.m16n8k16.row.col.f32.f16.f16.f32 "
        "{%0,%1,%2,%3}, {%4,%5,%6,%7}, {%8,%9}, {%0,%1,%2,%3};"
        : "+f"(d[0]), "+f"(d[1]), "+f"(d[2]), "+f"(d[3])
        : "r"(a[0]), "r"(a[1]), "r"(a[2]), "r"(a[3]), "r"(b[0]), "r"(b[1]));
}

// ---------------- prep: inputs -> fp16 ---------------------------------------
__global__ void prep_kernel(const float* __restrict__ i1, const float* __restrict__ i2) {
    const int idx = blockIdx.x * 256 + threadIdx.x;
    float4 a0 = ((const float4*)i1)[2 * idx];
    float4 a1 = ((const float4*)i1)[2 * idx + 1];
    __half2 h[4];
    h[0] = __floats2half2_rn(a0.x, a0.y); h[1] = __floats2half2_rn(a0.z, a0.w);
    h[2] = __floats2half2_rn(a1.x, a1.y); h[3] = __floats2half2_rn(a1.z, a1.w);
    ((uint4*)g_in1h)[idx] = *(const uint4*)h;
    float4 b0 = ((const float4*)i2)[2 * idx];
    float4 b1 = ((const float4*)i2)[2 * idx + 1];
    h[0] = __floats2half2_rn(b0.x, b0.y); h[1] = __floats2half2_rn(b0.z, b0.w);
    h[2] = __floats2half2_rn(b1.x, b1.y); h[3] = __floats2half2_rn(b1.z, b1.w);
    ((uint4*)g_in2h)[idx] = *(const uint4*)h;
}

// ---------------- convert w1 f32 -> fp16, same [k][n] layout -----------------
__global__ void convw_kernel(const float* __restrict__ W) {
    const size_t idx = (size_t)blockIdx.x * 256 + threadIdx.x;
    float4 a0 = ((const float4*)W)[2 * idx];
    float4 a1 = ((const float4*)W)[2 * idx + 1];
    __half2 h[4];
    h[0] = __floats2half2_rn(a0.x, a0.y); h[1] = __floats2half2_rn(a0.z, a0.w);
    h[2] = __floats2half2_rn(a1.x, a1.y); h[3] = __floats2half2_rn(a1.z, a1.w);
    ((uint4*)g_wh)[idx] = *(const uint4*)h;
}

// ---------------- terms (fp32, tiny) -----------------------------------------
__global__ void terms_kernel(const float* __restrict__ in1, const float* __restrict__ w2) {
    __shared__ float sIn[8][INs];
    const int r0 = blockIdx.x * 8;
    for (int i = threadIdx.x; i < 8 * INs; i += 128)
        sIn[i >> 9][i & 511] = in1[(size_t)r0 * INs + i];
    __syncthreads();
    const int o = threadIdx.x;
    if (o < OUTs) {
        float a[8], b[8];
#pragma unroll
        for (int r = 0; r < 8; ++r) { a[r] = 0.f; b[r] = 0.f; }
        for (int i = 0; i < INs; ++i) {
            const float wa = w2[i * OUTs + o];
            const float wb = w2[(INs + i) * OUTs + o];
#pragma unroll
            for (int r = 0; r < 8; ++r) {
                const float v = sIn[r][i];
                a[r] = fmaf(v, wa, a[r]);
                b[r] = fmaf(v, wb, b[r]);
            }
        }
        const float bias = w2[(size_t)(2 * INs) * OUTs + o];
#pragma unroll
        for (int r = 0; r < 8; ++r) {
            g_termA[(r0 + r) * OUTs + o] = a[r] + bias;
            g_termB[(r0 + r) * OUTs + o] = b[r];
        }
    }
}

// ---------------- stage 1: t = in1h @ W  (4 warps, warp tile 64x64) ----------
// CTA 128x128, K in 8 chunks of 64. A smem [128m][64k] 128B rows; B smem
// [64k][128n] 256B rows, unit swizzle. 3-stage cp.async.
#define S1_STAGE 32768
#define S1_SMEM  (3 * S1_STAGE)
__global__ __launch_bounds__(128, 2) void stage1_kernel() {
    extern __shared__ char sm[];
    const uint32_t smb = smem_u32(sm);
    const int tid = threadIdx.x;
    const int warp = tid >> 5, lane = tid & 31;
    const int g = lane >> 2, th = lane & 3;
    const int m0 = blockIdx.x << 7, n0 = blockIdx.y << 7;
    const int wm = (warp & 1) << 6;       // 0,64
    const int wn = (warp >> 1) << 6;      // 0,64

    const int l7   = lane & 7;
    const int a_r  = ((lane >> 3) & 1) * 8 + l7;
    const int a_us = (lane >> 4) & 1;
    const int bt_k = ((lane >> 3) & 1) * 8 + l7;
    const int bt_u = (wn >> 3) + ((lane >> 4) & 1);

    float acc[4][8][4];
#pragma unroll
    for (int mi = 0; mi < 4; ++mi)
#pragma unroll
        for (int ni = 0; ni < 8; ++ni)
#pragma unroll
            for (int r = 0; r < 4; ++r) acc[mi][ni][r] = 0.f;

    // A cp: 128 rows x 8 units, 8 per thread (row = 16i + tid>>3, u = tid&7)
    const int arow = tid >> 3, au = tid & 7;
    const __half* Asrc = g_in1h + (size_t)(m0 + arow) * INs + au * 8;
    const uint32_t cpa = smb + arow * 128 + ((au ^ (arow & 7)) << 4);
    // B cp: 64 k-rows x 16 units, 8 per thread (row = 8i + tid>>4, u = tid&15)
    const int brow = tid >> 4, bu = tid & 15;
    const __half* Bsrc = g_wh + (size_t)brow * N1 + n0 + bu * 8;
    const uint32_t cpb = smb + 16384 + brow * 256 + ((bu ^ (brow & 7)) << 4);

#define S1_ISSUE(s, c) do {                                                    \
    const uint32_t off = (s) * S1_STAGE;                                       \
    const int k0 = (c) << 6;                                                   \
    _Pragma("unroll")                                                          \
    for (int i = 0; i < 8; ++i)                                                \
        cp16(cpa + off + i * 2048, Asrc + (size_t)16 * i * INs + k0);          \
    _Pragma("unroll")                                                          \
    for (int i = 0; i < 8; ++i)                                                \
        cp16(cpb + off + i * 2048, Bsrc + (size_t)(k0 + 8 * i) * N1);          \
} while (0)

    S1_ISSUE(0, 0); CP_COMMIT();
    S1_ISSUE(1, 1); CP_COMMIT();
    int s = 0;
    for (int c = 0; c < 8; ++c) {
        if (c < 7) { CP_WAIT1(); } else { CP_WAIT0(); }
        __syncthreads();
        if (c < 6) {
            const int sn = (s + 2 >= 3) ? s - 1 : s + 2;
            S1_ISSUE(sn, c + 2); CP_COMMIT();
        }
        const uint32_t Ab = smb + s * S1_STAGE;
        const uint32_t Bb = Ab + 16384;
#pragma unroll
        for (int ks = 0; ks < 4; ++ks) {
            uint32_t af[4][4], bfp[4][4];
            const uint32_t axor = (uint32_t)(((ks * 2 + a_us) ^ l7) << 4);
#pragma unroll
            for (int mi = 0; mi < 4; ++mi)
                ldsm4(af[mi], Ab + (wm + mi * 16 + a_r) * 128 + axor);
#pragma unroll
            for (int p = 0; p < 4; ++p)
                ldsm4t(bfp[p], Bb + (ks * 16 + bt_k) * 256
                               + (uint32_t)(((bt_u + 2 * p) ^ l7) << 4));
#pragma unroll
            for (int mi = 0; mi < 4; ++mi)
#pragma unroll
                for (int ni = 0; ni < 8; ++ni)
                    mma16(acc[mi][ni], af[mi], &bfp[ni >> 1][(ni & 1) * 2]);
        }
        s = (s + 1 >= 3) ? 0 : s + 1;
    }

#pragma unroll
    for (int mi = 0; mi < 4; ++mi) {
        const int row = m0 + wm + mi * 16 + g;
#pragma unroll
        for (int ni = 0; ni < 8; ++ni) {
            const int col = n0 + wn + ni * 8 + 2 * th;
            *(__half2*)&g_th[(size_t)row * N1 + col] =
                __floats2half2_rn(acc[mi][ni][0], acc[mi][ni][1]);
            *(__half2*)&g_th[(size_t)(row + 8) * N1 + col] =
                __floats2half2_rn(acc[mi][ni][2], acc[mi][ni][3]);
        }
    }
}

// ---------------- stage 2: out = in2h @ t[bx]^T + terms (4 warps, 64x56) -----
#define S2_STAGE 30720
#define S2_SMEM  (3 * S2_STAGE)
__global__ __launch_bounds__(128, 2) void stage2_kernel(float* __restrict__ outp) {
    extern __shared__ char sm[];
    const uint32_t smb = smem_u32(sm);
    const int tid = threadIdx.x;
    const int warp = tid >> 5, lane = tid & 31;
    const int g = lane >> 2, th = lane & 3;
    const int y0 = blockIdx.x << 7;
    const int x  = blockIdx.y;
    const int b  = blockIdx.z;
    const size_t bx = (size_t)b * SS + x;
    const int wm = (warp & 1) << 6;      // 0,64
    const int wn = (warp >> 1) * 56;     // 0,56

    const int l7   = lane & 7;
    const int a_r  = ((lane >> 3) & 1) * 8 + l7;
    const int a_us = (lane >> 4) & 1;
    const int b_r  = ((lane >> 4) & 1) * 8 + l7;
    const int b_us = (lane >> 3) & 1;

    float acc[4][7][4];
#pragma unroll
    for (int mi = 0; mi < 4; ++mi)
#pragma unroll
        for (int ni = 0; ni < 7; ++ni)
#pragma unroll
            for (int r = 0; r < 4; ++r) acc[mi][ni][r] = 0.f;

    // A cp: 128 rows x 8 units, 8 per thread
    const int arow = tid >> 3, au = tid & 7;
    const __half* Asrc = g_in2h + ((size_t)b * SS + y0 + arow) * INs + au * 8;
    const uint32_t cpa = smb + arow * 128 + ((au ^ (arow & 7)) << 4);
    // B cp: 112 rows x 8 units = 896 units, 7 per thread (row = 16i + tid>>3)
    const __half* Bsrc = g_th + bx * N1 + (size_t)arow * INs + au * 8;
    const uint32_t cpb = smb + 16384 + arow * 128 + ((au ^ (arow & 7)) << 4);

#define S2_ISSUE(s, c) do {                                                    \
    const uint32_t off = (s) * S2_STAGE;                                       \
    const int k0 = (c) << 6;                                                   \
    _Pragma("unroll")                                                          \
    for (int i = 0; i < 8; ++i)                                                \
        cp16(cpa + off + i * 2048, Asrc + (size_t)16 * i * INs + k0);          \
    _Pragma("unroll")                                                          \
    for (int i = 0; i < 7; ++i)                                                \
        cp16(cpb + off + i * 2048, Bsrc + (size_t)16 * i * INs + k0);          \
} while (0)

    S2_ISSUE(0, 0); CP_COMMIT();
    S2_ISSUE(1, 1); CP_COMMIT();
    int s = 0;
    for (int c = 0; c < 8; ++c) {
        if (c < 7) { CP_WAIT1(); } else { CP_WAIT0(); }
        __syncthreads();
        if (c < 6) {
            const int sn = (s + 2 >= 3) ? s - 1 : s + 2;
            S2_ISSUE(sn, c + 2); CP_COMMIT();
        }
        const uint32_t Ab = smb + s * S2_STAGE;
        const uint32_t Bb = Ab + 16384;
#pragma unroll
        for (int ks = 0; ks < 4; ++ks) {
            uint32_t af[4][4], bf[8][2];
            const uint32_t axor = (uint32_t)(((ks * 2 + a_us) ^ l7) << 4);
            const uint32_t bxor = (uint32_t)(((ks * 2 + b_us) ^ l7) << 4);
#pragma unroll
            for (int mi = 0; mi < 4; ++mi)
                ldsm4(af[mi], Ab + (wm + mi * 16 + a_r) * 128 + axor);
#pragma unroll
            for (int p = 0; p < 3; ++p)
                ldsm4(bf[2 * p], Bb + (wn + p * 16 + b_r) * 128 + bxor);
            ldsm2(bf[6], Bb + (wn + 48 + l7) * 128 + bxor);
#pragma unroll
            for (int mi = 0; mi < 4; ++mi)
#pragma unroll
                for (int ni = 0; ni < 7; ++ni)
                    mma16(acc[mi][ni], af[mi], bf[ni]);
        }
        s = (s + 1 >= 3) ? 0 : s + 1;
    }

    const float* tA = g_termA + bx * OUTs;
#pragma unroll
    for (int mi = 0; mi < 4; ++mi) {
#pragma unroll
        for (int half = 0; half < 2; ++half) {
            const int row = y0 + wm + mi * 16 + g + 8 * half;
            const float* tB = g_termB + ((size_t)b * SS + row) * OUTs;
            float* orow = outp + (bx * SS + row) * OUTs;
#pragma unroll
            for (int ni = 0; ni < 7; ++ni) {
                const int col = wn + ni * 8 + 2 * th;
                const float2 a2 = *(const float2*)&tA[col];
                const float2 b2 = *(const float2*)&tB[col];
                float2 v;
                v.x = acc[mi][ni][2 * half + 0] + a2.x + b2.x;
                v.y = acc[mi][ni][2 * half + 1] + a2.y + b2.y;
                *(float2*)&orow[col] = v;
            }
        }
    }
}

// ---------------- launch -----------------------------------------------------
extern "C" void kernel_launch(void* const* d_in, const int* in_sizes, int n_in,
                              void* d_out, int out_size) {
    const float* in1 = (const float*)d_in[0];
    const float* in2 = (const float*)d_in[1];
    const float* w1  = (const float*)d_in[2];
    const float* w2  = (const float*)d_in[3];
    float* out = (float*)d_out;

    cudaFuncSetAttribute(stage1_kernel, cudaFuncAttributeMaxDynamicSharedMemorySize, S1_SMEM);
    cudaFuncSetAttribute(stage2_kernel, cudaFuncAttributeMaxDynamicSharedMemorySize, S2_SMEM);

    prep_kernel<<<1024, 256>>>(in1, in2);
    convw_kernel<<<14336, 256>>>(w1);
    terms_kernel<<<256, 128>>>(in1, w2);

    dim3 g1(16, 448);                    // m-tile fast: 16 CTAs share each B slab
    stage1_kernel<<<g1, 128, S1_SMEM>>>();

    dim3 g2(4, 512, 4);                  // y-tile fast: 4 CTAs share each t[bx]
    stage2_kernel<<<g2, 128, S2_SMEM>>>(out);
}